// round 3
// baseline (speedup 1.0000x reference)
#include <cuda_runtime.h>
#include <math.h>

#define L    8192
#define DIN  128
#define HH   64
#define WW   128
#define NCH  64
#define LC   128

// ---------------- scratch (device globals; no allocation) ----------------
__device__ float g_wpT [320 * 128];     // w_proj transposed [c][o]
__device__ float g_winT[128 * 256];     // w_in transposed   [c][o]
__device__ float g_woT [128 * 128];     // w_out transposed  [c][o]
__device__ float g_hxp[DIN * L];        // after w_proj GEMM       [o][l]
__device__ float g_xp [DIN * L];        // xp pre-conv             [d][l]
__device__ float g_zt [L * DIN];        // z                       [l][d]
__device__ float g_xsr[L * DIN];        // row-major scan input    [l][d]
__device__ float g_xsc[L * DIN];        // col-major scan input    [lc][d]
__device__ float g_dbc[4 * 40 * L];     // x_proj output           [k][r][l]
__device__ float g_dtv[4 * L * DIN];    // softplus dt             [k][l][d]
__device__ float g_bc [4 * L * 32];     // B(16),C(16) per pos     [k][l][32]
__device__ float g_S  [4 * DIN * NCH];          // sum dt per chunk
__device__ float g_F  [4 * DIN * NCH * 16];     // chunk-local final state
__device__ float g_hi [4 * DIN * NCH * 16];     // chunk initial state
__device__ float g_ys [4 * L * DIN];    // scan outputs            [k][l][d]
__device__ float g_ygT[DIN * L];        // merged+LN+gated, T      [d][l]
__device__ int   g_intA;

// ---------------- prep: transpose weights to [c][o] ----------------------
__global__ void k_prep(const float* __restrict__ wp,
                       const float* __restrict__ win,
                       const float* __restrict__ wout) {
    int i = blockIdx.x * 256 + threadIdx.x;
    if (i < 320 * 128) {
        int c = i >> 7, o = i & 127;
        g_wpT[i] = wp[o * 320 + c];
    } else if (i < 320 * 128 + 128 * 256) {
        int j = i - 320 * 128;
        int c = j >> 8, o = j & 255;
        g_winT[j] = win[o * 128 + c];
    } else if (i < 320 * 128 + 128 * 256 + 128 * 128) {
        int j = i - 320 * 128 - 128 * 256;
        int c = j >> 7, o = j & 127;
        g_woT[j] = wout[o * 128 + c];
    }
}

// ---------------- A-structure check: A_log == log(1..16)? ----------------
__global__ void k_checkA(const float* __restrict__ A_log) {
    __shared__ int bad;
    if (threadIdx.x == 0) bad = 0;
    __syncthreads();
    for (int i = threadIdx.x; i < 4 * DIN * 16; i += blockDim.x) {
        int n = i & 15;
        float ref = logf((float)(n + 1));
        if (fabsf(A_log[i] - ref) > 1e-5f) bad = 1;
    }
    __syncthreads();
    if (threadIdx.x == 0) g_intA = bad ? 0 : 1;
}

// ---------------- generic high-throughput GEMM ---------------------------
// out[o][l] = sum_c WT[c][o] * U[c][l]
// BL=128 (L), BO=64 (O). 256 threads: tx in [0,32) -> 4 l, ty in [0,8) -> 8 o.
// SRC: 0 = concat(h,x) args + g_wpT;  1 = g_hxp + g_winT;  2 = g_ygT + g_woT
// EPI: 0 = +bias -> g_hxp; 1 = split g_xp / g_zt(l-major); 2 = h + tanh -> out
template<int KDIM, int SRC, int EPI>
__global__ __launch_bounds__(256) void k_gemm(
    const float* __restrict__ U1, const float* __restrict__ U2,
    const float* __restrict__ bias, const float* __restrict__ hsrc,
    float* __restrict__ outp) {
    __shared__ float As[2][8][128];
    __shared__ float Bs[2][8][64];
    const float* WT = (SRC == 0) ? g_wpT : (SRC == 1) ? g_winT : g_woT;
    const int ostride = (SRC == 1) ? 256 : 128;
    int tid = threadIdx.x;
    int tx = tid & 31, ty = tid >> 5;
    int l0 = blockIdx.x * 128, o0 = blockIdx.y * 64;
    int ar = tid >> 5, ac = (tid & 31) * 4;
    int br = tid >> 4, bc = (tid & 15) * 4;
    float acc[4][8] = {};

    auto srcRow = [&](int c) -> const float* {
        if (SRC == 0) return (c < 128) ? (U1 + c * L) : (U2 + (c - 128) * L);
        else if (SRC == 1) return g_hxp + c * L;
        else return g_ygT + c * L;
    };

    *(float4*)&As[0][ar][ac] = *(const float4*)(srcRow(ar) + l0 + ac);
    if (tid < 128)
        *(float4*)&Bs[0][br][bc] = *(const float4*)(WT + br * ostride + o0 + bc);
    __syncthreads();

    const int nk = KDIM / 8;
#pragma unroll 1
    for (int t = 0; t < nk; t++) {
        int cur = t & 1, nxt = cur ^ 1;
        if (t + 1 < nk) {
            int k0 = (t + 1) * 8;
            *(float4*)&As[nxt][ar][ac] = *(const float4*)(srcRow(k0 + ar) + l0 + ac);
            if (tid < 128)
                *(float4*)&Bs[nxt][br][bc] =
                    *(const float4*)(WT + (k0 + br) * ostride + o0 + bc);
        }
#pragma unroll
        for (int kk = 0; kk < 8; kk++) {
            float4 a = *(float4*)&As[cur][kk][tx * 4];
            float4 b0 = *(float4*)&Bs[cur][kk][ty * 8];
            float4 b1 = *(float4*)&Bs[cur][kk][ty * 8 + 4];
            float av[4] = {a.x, a.y, a.z, a.w};
            float bv[8] = {b0.x, b0.y, b0.z, b0.w, b1.x, b1.y, b1.z, b1.w};
#pragma unroll
            for (int i = 0; i < 4; i++)
#pragma unroll
                for (int j = 0; j < 8; j++)
                    acc[i][j] = fmaf(av[i], bv[j], acc[i][j]);
        }
        __syncthreads();
    }

#pragma unroll
    for (int j = 0; j < 8; j++) {
        int o = o0 + ty * 8 + j;
        int off = o * L + l0 + tx * 4;
        float4 v = make_float4(acc[0][j], acc[1][j], acc[2][j], acc[3][j]);
        if (EPI == 0) {
            float bv = bias[o];
            v.x += bv; v.y += bv; v.z += bv; v.w += bv;
            *(float4*)(g_hxp + off) = v;
        } else if (EPI == 1) {
            if (o < 128) {
                *(float4*)(g_xp + off) = v;
            } else {
                int dz = o - 128;
                int lb = l0 + tx * 4;
                g_zt[(lb + 0) * DIN + dz] = v.x;
                g_zt[(lb + 1) * DIN + dz] = v.y;
                g_zt[(lb + 2) * DIN + dz] = v.z;
                g_zt[(lb + 3) * DIN + dz] = v.w;
            }
        } else {
            float4 hv = *(const float4*)(hsrc + off);
            v.x = hv.x + tanhf(v.x);
            v.y = hv.y + tanhf(v.y);
            v.z = hv.z + tanhf(v.z);
            v.w = hv.w + tanhf(v.w);
            *(float4*)(outp + off) = v;
        }
    }
}

// ------------- fused depthwise 3x3 conv + SiLU + transpose ---------------
__global__ void k_convt(const float* __restrict__ wc,
                        const float* __restrict__ bcv) {
    __shared__ float t[32][33];
    int l0 = blockIdx.x * 32, d0 = blockIdx.y * 32;
    int tx = threadIdx.x, ty = threadIdx.y;  // 32 x 8
    int l = l0 + tx;
    int hh = l >> 7, ww = l & 127;
#pragma unroll
    for (int j = 0; j < 4; j++) {
        int d = d0 + ty + 8 * j;
        const float* src = g_xp + (d << 13);
        const float* w9 = wc + d * 9;
        float acc = bcv[d];
#pragma unroll
        for (int kh = 0; kh < 3; kh++) {
            int y = hh + kh - 1;
            if (y < 0 || y >= HH) continue;
#pragma unroll
            for (int kw = 0; kw < 3; kw++) {
                int xw = ww + kw - 1;
                if (xw < 0 || xw >= WW) continue;
                acc = fmaf(src[y * WW + xw], w9[kh * 3 + kw], acc);
            }
        }
        t[ty + 8 * j][tx] = acc / (1.f + __expf(-acc));
    }
    __syncthreads();
#pragma unroll
    for (int j = 0; j < 4; j++) {
        int l2 = l0 + ty + 8 * j;
        float v = t[tx][ty + 8 * j];
        g_xsr[l2 * DIN + d0 + tx] = v;
        int h2 = l2 >> 7, w2 = l2 & 127;
        g_xsc[(w2 * HH + h2) * DIN + d0 + tx] = v;
    }
}

// ---------------- x_proj: dbc[k] = x_proj_w[k] @ xs[k]  (NT GEMM) --------
__global__ __launch_bounds__(256) void k_dbc(const float* __restrict__ xpw) {
    int k = blockIdx.z;
    const float* A = xpw + k * 40 * 128;
    const float* Bsrc = (k & 1) ? g_xsc : g_xsr;
    bool rev = (k >= 2);
    __shared__ float As[16][64];
    __shared__ float Bs[16][64];
    int tid = threadIdx.x;
    int tx = tid & 15, ty = tid >> 4;
    int l0 = blockIdx.x * 64;
    int arow = tid >> 2, ak = (tid & 3) * 4;
    float acc[4][4] = {};
    for (int k0 = 0; k0 < 128; k0 += 16) {
        int rr = arow < 40 ? arow : 39;
        float4 av = *(const float4*)(A + rr * 128 + k0 + ak);
        As[ak + 0][arow] = av.x; As[ak + 1][arow] = av.y;
        As[ak + 2][arow] = av.z; As[ak + 3][arow] = av.w;
        int ln = l0 + arow;
        int lsrc = rev ? (L - 1 - ln) : ln;
        float4 bv = *(const float4*)(Bsrc + lsrc * 128 + k0 + ak);
        Bs[ak + 0][arow] = bv.x; Bs[ak + 1][arow] = bv.y;
        Bs[ak + 2][arow] = bv.z; Bs[ak + 3][arow] = bv.w;
        __syncthreads();
#pragma unroll
        for (int kk = 0; kk < 16; kk++) {
            float4 a = *(float4*)&As[kk][ty * 4];
            float4 b = *(float4*)&Bs[kk][tx * 4];
            float ar[4] = {a.x, a.y, a.z, a.w};
            float br[4] = {b.x, b.y, b.z, b.w};
#pragma unroll
            for (int r = 0; r < 4; r++)
#pragma unroll
                for (int cc = 0; cc < 4; cc++)
                    acc[r][cc] = fmaf(ar[r], br[cc], acc[r][cc]);
        }
        __syncthreads();
    }
#pragma unroll
    for (int r = 0; r < 4; r++) {
        int m = ty * 4 + r;
        if (m < 40) {
#pragma unroll
            for (int cc = 0; cc < 4; cc++)
                g_dbc[(k * 40 + m) * L + l0 + tx * 4 + cc] = acc[r][cc];
        }
    }
}

// ---------------- dt = softplus(dt_w @ dts + dt_b); pack B,C -------------
__global__ __launch_bounds__(128) void k_dt(
    const float* __restrict__ dtw, const float* __restrict__ dtbias) {
    int k = blockIdx.y;
    int l0 = blockIdx.x * 32;
    int d = threadIdx.x;
    __shared__ float sd[40][33];
    for (int i = threadIdx.x; i < 40 * 32; i += 128) {
        int r = i >> 5, j = i & 31;
        sd[r][j] = g_dbc[(k * 40 + r) * L + l0 + j];
    }
    __syncthreads();
    float wreg[8];
#pragma unroll
    for (int r = 0; r < 8; r++) wreg[r] = dtw[(k * DIN + d) * 8 + r];
    float bv = dtbias[k * DIN + d];
    for (int j = 0; j < 32; j++) {
        float acc = bv;
#pragma unroll
        for (int r = 0; r < 8; r++) acc = fmaf(wreg[r], sd[r][j], acc);
        float sp = (acc > 20.f) ? acc : log1pf(__expf(acc));
        g_dtv[(k * L + l0 + j) * DIN + d] = sp;
    }
    for (int i = threadIdx.x; i < 32 * 32; i += 128) {
        int n = i >> 5, j = i & 31;
        g_bc[(k * L + l0 + j) * 32 + n] = sd[8 + n][j];
    }
}

// ---------------- a_n = exp(dt * A_n) helpers ----------------------------
__device__ __forceinline__ void compute_a(float dtv, const float* An, bool ia,
                                          float* a) {
    if (ia) {
        float r1 = __expf(-dtv);
        float r2 = r1 * r1, r4 = r2 * r2, r8 = r4 * r4;
        a[0] = r1;       a[1] = r2;       a[2] = r2 * r1;  a[3] = r4;
        a[4] = r4 * r1;  a[5] = r4 * r2;  a[6] = r4 * a[2]; a[7] = r8;
        a[8] = r8 * r1;  a[9] = r8 * r2;  a[10] = r8 * a[2]; a[11] = r8 * r4;
        a[12] = r8 * a[4]; a[13] = r8 * a[5]; a[14] = r8 * a[6]; a[15] = r8 * r8;
    } else {
#pragma unroll
        for (int n = 0; n < 16; n++) a[n] = __expf(An[n] * dtv);
    }
}

// ---------------- scan phase 1: chunk-local (F, sum-dt) ------------------
__global__ __launch_bounds__(128) void k_scan1(const float* __restrict__ A_log) {
    int c = blockIdx.x, k = blockIdx.y, d = threadIdx.x;
    bool ia = (g_intA != 0);
    float An[16];
    if (!ia) {
#pragma unroll
        for (int n = 0; n < 16; n++) An[n] = -__expf(A_log[(k * DIN + d) * 16 + n]);
    }
    const float* usrc = (k & 1) ? g_xsc : g_xsr;
    bool rev = (k >= 2);
    float hr[16];
#pragma unroll
    for (int n = 0; n < 16; n++) hr[n] = 0.f;
    float S = 0.f;
    const float* dtp = g_dtv + k * L * DIN;
    for (int i = 0; i < LC; i++) {
        int l = c * LC + i;
        float dtv = dtp[l * DIN + d];
        int lu = rev ? (L - 1 - l) : l;
        float uv = usrc[lu * DIN + d];
        float du = dtv * uv;
        S += dtv;
        const float4* bp = (const float4*)(g_bc + (k * L + l) * 32);
        float4 b0 = bp[0], b1 = bp[1], b2 = bp[2], b3 = bp[3];
        float bb[16] = {b0.x, b0.y, b0.z, b0.w, b1.x, b1.y, b1.z, b1.w,
                        b2.x, b2.y, b2.z, b2.w, b3.x, b3.y, b3.z, b3.w};
        float a[16];
        compute_a(dtv, An, ia, a);
#pragma unroll
        for (int n = 0; n < 16; n++) hr[n] = fmaf(a[n], hr[n], du * bb[n]);
    }
    int base = (k * DIN + d) * NCH + c;
    g_S[base] = S;
#pragma unroll
    for (int n = 0; n < 16; n++) g_F[base * 16 + n] = hr[n];
}

// ---------------- scan phase 2: cross-chunk prefix -----------------------
__global__ __launch_bounds__(256) void k_scan2(const float* __restrict__ A_log) {
    int n = threadIdx.x & 15;
    int d = blockIdx.x * 16 + (threadIdx.x >> 4);
    int k = blockIdx.y;
    bool ia = (g_intA != 0);
    float An = ia ? -(float)(n + 1) : -__expf(A_log[(k * DIN + d) * 16 + n]);
    float h = 0.f;
    int base = (k * DIN + d) * NCH;
    for (int c = 0; c < NCH; c++) {
        g_hi[(base + c) * 16 + n] = h;
        float P = __expf(An * g_S[base + c]);
        h = fmaf(P, h, g_F[(base + c) * 16 + n]);
    }
}

// ---------------- scan phase 3: replay with init, emit y -----------------
__global__ __launch_bounds__(128) void k_scan3(
    const float* __restrict__ A_log, const float* __restrict__ Dssm) {
    int c = blockIdx.x, k = blockIdx.y, d = threadIdx.x;
    bool ia = (g_intA != 0);
    float An[16];
    if (!ia) {
#pragma unroll
        for (int n = 0; n < 16; n++) An[n] = -__expf(A_log[(k * DIN + d) * 16 + n]);
    }
    const float* usrc = (k & 1) ? g_xsc : g_xsr;
    bool rev = (k >= 2);
    float Dv = Dssm[k * DIN + d];
    int base = (k * DIN + d) * NCH + c;
    float hr[16];
#pragma unroll
    for (int n = 0; n < 16; n++) hr[n] = g_hi[base * 16 + n];
    const float* dtp = g_dtv + k * L * DIN;
    for (int i = 0; i < LC; i++) {
        int l = c * LC + i;
        float dtv = dtp[l * DIN + d];
        int lu = rev ? (L - 1 - l) : l;
        float uv = usrc[lu * DIN + d];
        float du = dtv * uv;
        const float4* bp = (const float4*)(g_bc + (k * L + l) * 32);
        float4 b0 = bp[0], b1 = bp[1], b2 = bp[2], b3 = bp[3];
        float4 c0 = bp[4], c1 = bp[5], c2 = bp[6], c3 = bp[7];
        float bb[16] = {b0.x, b0.y, b0.z, b0.w, b1.x, b1.y, b1.z, b1.w,
                        b2.x, b2.y, b2.z, b2.w, b3.x, b3.y, b3.z, b3.w};
        float cc[16] = {c0.x, c0.y, c0.z, c0.w, c1.x, c1.y, c1.z, c1.w,
                        c2.x, c2.y, c2.z, c2.w, c3.x, c3.y, c3.z, c3.w};
        float a[16];
        compute_a(dtv, An, ia, a);
        float y4[4] = {0.f, 0.f, 0.f, 0.f};
#pragma unroll
        for (int n = 0; n < 16; n++) {
            hr[n] = fmaf(a[n], hr[n], du * bb[n]);
            y4[n & 3] = fmaf(hr[n], cc[n], y4[n & 3]);
        }
        float y = fmaf(Dv, uv, (y4[0] + y4[1]) + (y4[2] + y4[3]));
        g_ys[(k * L + l) * DIN + d] = y;
    }
}

// ---------------- cross-merge + LN + SiLU(z) gate -> ygT[d][l] -----------
__global__ __launch_bounds__(256) void k_merge(
    const float* __restrict__ lng, const float* __restrict__ lnb) {
    __shared__ float ts[32][133];
    int l0 = blockIdx.x * 32;
    int lane = threadIdx.x & 31, w = threadIdx.x >> 5;
    float g4[4], b4[4];
    *(float4*)g4 = *(const float4*)(lng + lane * 4);
    *(float4*)b4 = *(const float4*)(lnb + lane * 4);
#pragma unroll
    for (int q = 0; q < 4; q++) {
        int ll = w * 4 + q;
        int l = l0 + ll;
        int hh = l >> 7, ww = l & 127;
        int lc = ww * HH + hh;
        float4 y0 = *(const float4*)(g_ys + (0 * L + l) * DIN + lane * 4);
        float4 y2 = *(const float4*)(g_ys + (2 * L + (L - 1 - l)) * DIN + lane * 4);
        float4 y1 = *(const float4*)(g_ys + (1 * L + lc) * DIN + lane * 4);
        float4 y3 = *(const float4*)(g_ys + (3 * L + (L - 1 - lc)) * DIN + lane * 4);
        float yv[4] = {y0.x + y2.x + y1.x + y3.x, y0.y + y2.y + y1.y + y3.y,
                       y0.z + y2.z + y1.z + y3.z, y0.w + y2.w + y1.w + y3.w};
        float s = yv[0] + yv[1] + yv[2] + yv[3];
        float s2 = yv[0] * yv[0] + yv[1] * yv[1] + yv[2] * yv[2] + yv[3] * yv[3];
#pragma unroll
        for (int o = 16; o > 0; o >>= 1) {
            s  += __shfl_xor_sync(0xffffffffu, s, o);
            s2 += __shfl_xor_sync(0xffffffffu, s2, o);
        }
        float mu = s * (1.f / 128.f);
        float var = s2 * (1.f / 128.f) - mu * mu;
        float rstd = rsqrtf(var + 1e-5f);
        float4 zv = *(const float4*)(g_zt + l * DIN + lane * 4);
        float zz[4] = {zv.x, zv.y, zv.z, zv.w};
#pragma unroll
        for (int m = 0; m < 4; m++) {
            float gv = (yv[m] - mu) * rstd * g4[m] + b4[m];
            float sz = zz[m] / (1.f + __expf(-zz[m]));
            ts[ll][lane * 4 + m] = gv * sz;
        }
    }
    __syncthreads();
    int d = threadIdx.x >> 1;
    int cb = (threadIdx.x & 1) * 16;
#pragma unroll
    for (int i = 0; i < 16; i += 4) {
        float4 v = make_float4(ts[cb + i + 0][d], ts[cb + i + 1][d],
                               ts[cb + i + 2][d], ts[cb + i + 3][d]);
        *(float4*)(g_ygT + d * L + l0 + cb + i) = v;
    }
}

// ---------------- launch ----------------
extern "C" void kernel_launch(void* const* d_in, const int* in_sizes, int n_in,
                              void* d_out, int out_size) {
    const float* h       = (const float*)d_in[0];
    const float* x       = (const float*)d_in[1];
    const float* w_proj  = (const float*)d_in[2];
    const float* b_proj  = (const float*)d_in[3];
    const float* w_in    = (const float*)d_in[4];
    const float* w_conv  = (const float*)d_in[5];
    const float* b_conv  = (const float*)d_in[6];
    const float* x_proj_w= (const float*)d_in[7];
    const float* dt_w    = (const float*)d_in[8];
    const float* dt_b    = (const float*)d_in[9];
    const float* A_log   = (const float*)d_in[10];
    const float* D_ssm   = (const float*)d_in[11];
    const float* ln_g    = (const float*)d_in[12];
    const float* ln_b    = (const float*)d_in[13];
    const float* w_out   = (const float*)d_in[14];
    float* out = (float*)d_out;

    k_prep  <<<(320*128 + 128*256 + 128*128 + 255) / 256, 256>>>(w_proj, w_in, w_out);
    k_checkA<<<1, 256>>>(A_log);
    // GEMM1: hxp = w_proj @ concat(h,x) + b_proj   (K=320, O=128)
    k_gemm<320, 0, 0><<<dim3(64, 2), 256>>>(h, x, b_proj, nullptr, nullptr);
    // GEMM2: [xp; z] = w_in @ hxp                  (K=128, O=256)
    k_gemm<128, 1, 1><<<dim3(64, 4), 256>>>(nullptr, nullptr, nullptr, nullptr, nullptr);
    k_convt <<<dim3(256, 4), dim3(32, 8)>>>(w_conv, b_conv);
    k_dbc   <<<dim3(128, 1, 4), 256>>>(x_proj_w);
    k_dt    <<<dim3(256, 4), 128>>>(dt_w, dt_b);
    k_scan1 <<<dim3(NCH, 4), 128>>>(A_log);
    k_scan2 <<<dim3(8, 4), 256>>>(A_log);
    k_scan3 <<<dim3(NCH, 4), 128>>>(A_log, D_ssm);
    k_merge <<<256, 256>>>(ln_g, ln_b);
    // FINAL: out = h + tanh(w_out @ ygT)           (K=128, O=128)
    k_gemm<128, 2, 2><<<dim3(64, 2), 256>>>(nullptr, nullptr, nullptr, h, out);
}